// round 14
// baseline (speedup 1.0000x reference)
#include <cuda_runtime.h>
#include <stdint.h>

#define BB 16384
#define TT 128

// ---------------------------------------------------------------------------
// 256-bit global accesses (sm_100+): ld/st.global.v8.b32
// ---------------------------------------------------------------------------
__device__ __forceinline__ void ldg256(const float* p, float* v) {
    asm("ld.global.nc.v8.b32 {%0,%1,%2,%3,%4,%5,%6,%7}, [%8];"
        : "=f"(v[0]), "=f"(v[1]), "=f"(v[2]), "=f"(v[3]),
          "=f"(v[4]), "=f"(v[5]), "=f"(v[6]), "=f"(v[7])
        : "l"(p));
}
__device__ __forceinline__ void stg256(float* p, const float* v) {
    asm volatile("st.global.v8.b32 [%0], {%1,%2,%3,%4,%5,%6,%7,%8};"
                 :: "l"(p),
                    "f"(v[0]), "f"(v[1]), "f"(v[2]), "f"(v[3]),
                    "f"(v[4]), "f"(v[5]), "f"(v[6]), "f"(v[7])
                 : "memory");
}

// ---------------------------------------------------------------------------
// JAX threefry2x32 (exact integer reproduction, partitionable scheme)
// ---------------------------------------------------------------------------
__host__ __device__ __forceinline__ uint32_t rotl32(uint32_t x, int d) {
    return (x << d) | (x >> (32 - d));
}

__host__ __device__ __forceinline__ void threefry2x32(uint32_t k0, uint32_t k1,
                                                      uint32_t& x0, uint32_t& x1) {
    uint32_t k2 = k0 ^ k1 ^ 0x1BD11BDAu;
    x0 += k0; x1 += k1;
#define TF_R(r) { x0 += x1; x1 = rotl32(x1, (r)); x1 ^= x0; }
    TF_R(13) TF_R(15) TF_R(26) TF_R(6)
    x0 += k1; x1 += k2 + 1u;
    TF_R(17) TF_R(29) TF_R(16) TF_R(24)
    x0 += k2; x1 += k0 + 2u;
    TF_R(13) TF_R(15) TF_R(26) TF_R(6)
    x0 += k0; x1 += k1 + 3u;
    TF_R(17) TF_R(29) TF_R(16) TF_R(24)
    x0 += k1; x1 += k2 + 4u;
    TF_R(13) TF_R(15) TF_R(26) TF_R(6)
    x0 += k2; x1 += k0 + 5u;
#undef TF_R
}

// jax.random.uniform(key,(B,),f32)[b] under jax_threefry_partitionable=True
__device__ __forceinline__ float jax_uniform_at(uint32_t ka, uint32_t kb, int b) {
    uint32_t x0 = 0u, x1 = (uint32_t)b;
    threefry2x32(ka, kb, x0, x1);
    uint32_t bits = x0 ^ x1;
    uint32_t f = (bits >> 9) | 0x3F800000u;
    return __uint_as_float(f) - 1.0f;
}

// ---------------------------------------------------------------------------
// Warp = TWO rows. Lanes 0..15 -> row b0, lanes 16..31 -> row b1.
// Each lane handles 8 tokens: pos = 96 B = 3 x 256-bit, quat = 128 B =
// 2 chunks of 2 x 256-bit. ALL global I/O is 256-bit.
// Block = 128 threads = 4 warps = 8 rows; grid = BB/8.
// ---------------------------------------------------------------------------
__global__ __launch_bounds__(128) void rot_randomizer_kernel(
    const float* __restrict__ pos,   // [B,T,3]
    const float* __restrict__ quat,  // [B,T,4] xyzw
    float* __restrict__ pos_out,     // [B,T,3]
    float* __restrict__ quat_out,    // [B,T,4] xyzw
    float* __restrict__ R_out,       // [B,3,3]
    uint32_t k0a, uint32_t k0b, uint32_t k1a, uint32_t k1b,
    uint32_t k2a, uint32_t k2b, uint32_t k3a, uint32_t k3b)
{
    const int warp = threadIdx.x >> 5;
    const int lane = threadIdx.x & 31;
    const int b0 = (blockIdx.x * 4 + warp) * 2;
    const int half = lane >> 4;    // 0 -> row b0, 1 -> row b1
    const int sl   = lane & 15;    // sub-lane within half-warp
    const int b    = b0 + half;
    const unsigned FULL = 0xFFFFFFFFu;

    // ---------- RNG: 8 uniforms (4 per row) on lanes 0..7 ----------
    float u = 0.0f;
    if (lane < 8) {
        const int kidx = lane & 3;
        const int row  = b0 + (lane >> 2);
        uint32_t ka = (kidx == 0) ? k0a : (kidx == 1) ? k1a : (kidx == 2) ? k2a : k3a;
        uint32_t kb = (kidx == 0) ? k0b : (kidx == 1) ? k1b : (kidx == 2) ? k2b : k3b;
        u = jax_uniform_at(ka, kb, row);
    }
    // both rows' uniforms (needed to build sincos inputs on lanes 0..11)
    const float u0_0 = __shfl_sync(FULL, u, 0);
    const float u1_0 = __shfl_sync(FULL, u, 1);
    const float u2_0 = __shfl_sync(FULL, u, 2);
    const float u3_0 = __shfl_sync(FULL, u, 3);
    const float u0_1 = __shfl_sync(FULL, u, 4);
    const float u1_1 = __shfl_sync(FULL, u, 5);
    const float u2_1 = __shfl_sync(FULL, u, 6);
    const float u3_1 = __shfl_sync(FULL, u, 7);

    const float PI_F = 3.14159265358979323846f;
    const bool mask0 = u3_0 < 0.015625f;
    const bool mask1 = u3_1 < 0.015625f;
    const float ax0 = mask0 ? 0.0f : ((u0_0 * 2.0f) * PI_F - PI_F);
    const float ay0 = mask0 ? 0.0f : ((u1_0 * 2.0f) * PI_F - PI_F);
    const float az0 = mask0 ? 0.0f : ((u2_0 * 2.0f) * PI_F - PI_F);
    const float ax1 = mask1 ? 0.0f : ((u0_1 * 2.0f) * PI_F - PI_F);
    const float ay1 = mask1 ? 0.0f : ((u1_1 * 2.0f) * PI_F - PI_F);
    const float az1 = mask1 ? 0.0f : ((u2_1 * 2.0f) * PI_F - PI_F);

    // ---------- 12 accurate sincos on lanes 0..11 ----------
    // lanes 0..5: row b0 {ax,ay,az,ax/2,ay/2,az/2}; lanes 6..11: row b1.
    // (fast __sincosf flips argmax sign decisions -> correctness failure)
    float amine = 0.0f;
    if (lane < 12) {
        const bool r1 = lane >= 6;
        const int l6 = r1 ? lane - 6 : lane;
        const float AX = r1 ? ax1 : ax0;
        const float AY = r1 ? ay1 : ay0;
        const float AZ = r1 ? az1 : az0;
        amine = (l6 == 0) ? AX : (l6 == 1) ? AY : (l6 == 2) ? AZ :
                (l6 == 3) ? 0.5f * AX : (l6 == 4) ? 0.5f * AY : 0.5f * AZ;
    }
    float s_, c_;
    sincosf(amine, &s_, &c_);

    // each lane fetches only ITS row's sin/cos (base = half*6)
    const int sb = half * 6;
    const float sx  = __shfl_sync(FULL, s_, sb + 0), cx  = __shfl_sync(FULL, c_, sb + 0);
    const float sy  = __shfl_sync(FULL, s_, sb + 1), cy  = __shfl_sync(FULL, c_, sb + 1);
    const float sz  = __shfl_sync(FULL, s_, sb + 2), cz  = __shfl_sync(FULL, c_, sb + 2);
    const float sx2 = __shfl_sync(FULL, s_, sb + 3), cx2 = __shfl_sync(FULL, c_, sb + 3);
    const float sy2 = __shfl_sync(FULL, s_, sb + 4), cy2 = __shfl_sync(FULL, c_, sb + 4);
    const float sz2 = __shfl_sync(FULL, s_, sb + 5), cz2 = __shfl_sync(FULL, c_, sb + 5);

    // --- R = (Rz @ Ry) @ Rx  (own row) ---
    const float r00 = cz * cy;
    const float r01 = (cz * sy) * sx - sz * cx;
    const float r02 = (cz * sy) * cx + sz * sx;
    const float r10 = sz * cy;
    const float r11 = (sz * sy) * sx + cz * cx;
    const float r12 = (sz * sy) * cx - cz * sx;
    const float r20 = -sy;
    const float r21 = cy * sx;
    const float r22 = cy * cx;

    if (sl == 0) {  // lane 0 writes b0's R, lane 16 writes b1's R
        float* Ro = R_out + b * 9;
        Ro[0] = r00; Ro[1] = r01; Ro[2] = r02;
        Ro[3] = r10; Ro[4] = r11; Ro[5] = r12;
        Ro[6] = r20; Ro[7] = r21; Ro[8] = r22;
    }

    // --- r_q = quat(Rz) (x) quat(Ry) (x) quat(Rx), wxyz (own row) ---
    const float w1  = cy2 * cx2;
    const float x1q = cy2 * sx2;
    const float y1q = cx2 * sy2;
    const float z1q = -sy2 * sx2;
    const float rw = cz2 * w1  - sz2 * z1q;
    const float rx = cz2 * x1q - sz2 * y1q;
    const float ry = cz2 * y1q + sz2 * x1q;
    const float rz = cz2 * z1q + sz2 * w1;

    // ---------------- positions: 8 tokens = 3 x 256-bit ----------------
    {
        const int poff = b * (TT * 3) + sl * 24;   // floats; 96 B stride
        float pin[24], pout[24];
        ldg256(pos + poff,      pin);
        ldg256(pos + poff + 8,  pin + 8);
        ldg256(pos + poff + 16, pin + 16);

#pragma unroll
        for (int t = 0; t < 8; t++) {
            const float X = pin[t * 3 + 0];
            const float Y = pin[t * 3 + 1];
            const float Z = pin[t * 3 + 2];
            pout[t * 3 + 0] = r00 * X + r01 * Y + r02 * Z;
            pout[t * 3 + 1] = r10 * X + r11 * Y + r12 * Z;
            pout[t * 3 + 2] = r20 * X + r21 * Y + r22 * Z;
        }

        stg256(pos_out + poff,      pout);
        stg256(pos_out + poff + 8,  pout + 8);
        stg256(pos_out + poff + 16, pout + 16);
    }

    // ---------------- quats: 8 tokens = 2 chunks x (2 x 256-bit) ----------
    {
        const int qoff = b * (TT * 4) + sl * 32;   // floats; 128 B stride
#pragma unroll
        for (int c = 0; c < 2; c++) {
            float qin[16], qout[16];
            ldg256(quat + qoff + c * 16,     qin);
            ldg256(quat + qoff + c * 16 + 8, qin + 8);

#pragma unroll
            for (int j = 0; j < 4; j++) {
                const float qx = qin[j * 4 + 0], qy = qin[j * 4 + 1],
                            qz = qin[j * 4 + 2], qw = qin[j * 4 + 3];  // xyzw

                // p = r_q (x) q   (wxyz)
                const float pw = rw * qw - rx * qx - ry * qy - rz * qz;
                const float px = rw * qx + rx * qw + ry * qz - rz * qy;
                const float py = rw * qy - rx * qz + ry * qw + rz * qx;
                const float pz = rw * qz + rx * qy - ry * qx + rz * qw;

                // first-max argmax over |pw|,|px|,|py|,|pz| -> sign canon.
                const float aw = fabsf(pw), axv = fabsf(px),
                            ayv = fabsf(py), azv = fabsf(pz);
                float bv = aw, bs = pw;
                if (axv > bv) { bv = axv; bs = px; }
                if (ayv > bv) { bv = ayv; bs = py; }
                if (azv > bv) { bv = azv; bs = pz; }

                const float n2 = qx * qx + qy * qy + qz * qz + qw * qw;
                float f = rsqrtf(n2);
                f = (bs < 0.0f) ? -f : f;

                qout[j * 4 + 0] = px * f;
                qout[j * 4 + 1] = py * f;
                qout[j * 4 + 2] = pz * f;
                qout[j * 4 + 3] = pw * f;  // xyzw
            }

            stg256(quat_out + qoff + c * 16,     qout);
            stg256(quat_out + qoff + c * 16 + 8, qout + 8);
        }
    }
}

// ---------------------------------------------------------------------------
// Host: derive the four _build_R keys from seed 42 (partitionable threefry)
// ---------------------------------------------------------------------------
static void host_threefry(uint32_t k0, uint32_t k1, uint32_t x0, uint32_t x1,
                          uint32_t* o0, uint32_t* o1) {
    threefry2x32(k0, k1, x0, x1);
    *o0 = x0; *o1 = x1;
}

extern "C" void kernel_launch(void* const* d_in, const int* in_sizes, int n_in,
                              void* d_out, int out_size) {
    const float* pos  = (const float*)d_in[0];
    const float* quat = (const float*)d_in[1];
    float* out = (float*)d_out;

    // key = jax.random.key(42) -> (0, 42); sub = split(key)[1]
    uint32_t sa, sb;
    host_threefry(0u, 42u, 0u, 1u, &sa, &sb);

    // k = split(sub, 4): k[j] = full output pair of threefry(sub; 0, j)
    uint32_t kj[4][2];
    for (uint32_t j = 0; j < 4; j++) {
        host_threefry(sa, sb, 0u, j, &kj[j][0], &kj[j][1]);
    }

    float* pos_out  = out;
    float* quat_out = out + (size_t)BB * TT * 3;
    float* R_out    = out + (size_t)BB * TT * 7;

    rot_randomizer_kernel<<<BB / 8, 128>>>(
        pos, quat, pos_out, quat_out, R_out,
        kj[0][0], kj[0][1],
        kj[1][0], kj[1][1],
        kj[2][0], kj[2][1],
        kj[3][0], kj[3][1]);
}

// round 15
// speedup vs baseline: 1.2073x; 1.2073x over previous
#include <cuda_runtime.h>
#include <stdint.h>

#define BB 16384
#define TT 128

// ---------------------------------------------------------------------------
// 256-bit global accesses (sm_100+): ld/st.global.v8.b32
// volatile: pin issue order so the quat loads stay hoisted into the pos
// load wave (ptxas otherwise sinks them to first use).
// ---------------------------------------------------------------------------
__device__ __forceinline__ void ldg256(const float* p, float* v) {
    asm volatile("ld.global.nc.v8.b32 {%0,%1,%2,%3,%4,%5,%6,%7}, [%8];"
        : "=f"(v[0]), "=f"(v[1]), "=f"(v[2]), "=f"(v[3]),
          "=f"(v[4]), "=f"(v[5]), "=f"(v[6]), "=f"(v[7])
        : "l"(p));
}
__device__ __forceinline__ void stg256(float* p, const float* v) {
    asm volatile("st.global.v8.b32 [%0], {%1,%2,%3,%4,%5,%6,%7,%8};"
                 :: "l"(p),
                    "f"(v[0]), "f"(v[1]), "f"(v[2]), "f"(v[3]),
                    "f"(v[4]), "f"(v[5]), "f"(v[6]), "f"(v[7])
                 : "memory");
}

// ---------------------------------------------------------------------------
// JAX threefry2x32 (exact integer reproduction, partitionable scheme)
// ---------------------------------------------------------------------------
__host__ __device__ __forceinline__ uint32_t rotl32(uint32_t x, int d) {
    return (x << d) | (x >> (32 - d));
}

__host__ __device__ __forceinline__ void threefry2x32(uint32_t k0, uint32_t k1,
                                                      uint32_t& x0, uint32_t& x1) {
    uint32_t k2 = k0 ^ k1 ^ 0x1BD11BDAu;
    x0 += k0; x1 += k1;
#define TF_R(r) { x0 += x1; x1 = rotl32(x1, (r)); x1 ^= x0; }
    TF_R(13) TF_R(15) TF_R(26) TF_R(6)
    x0 += k1; x1 += k2 + 1u;
    TF_R(17) TF_R(29) TF_R(16) TF_R(24)
    x0 += k2; x1 += k0 + 2u;
    TF_R(13) TF_R(15) TF_R(26) TF_R(6)
    x0 += k0; x1 += k1 + 3u;
    TF_R(17) TF_R(29) TF_R(16) TF_R(24)
    x0 += k1; x1 += k2 + 4u;
    TF_R(13) TF_R(15) TF_R(26) TF_R(6)
    x0 += k2; x1 += k0 + 5u;
#undef TF_R
}

// jax.random.uniform(key,(B,),f32)[b] under jax_threefry_partitionable=True
__device__ __forceinline__ float jax_uniform_at(uint32_t ka, uint32_t kb, int b) {
    uint32_t x0 = 0u, x1 = (uint32_t)b;
    threefry2x32(ka, kb, x0, x1);
    uint32_t bits = x0 ^ x1;
    uint32_t f = (bits >> 9) | 0x3F800000u;
    return __uint_as_float(f) - 1.0f;
}

// ---------------------------------------------------------------------------
// One warp per batch row; each lane handles 4 tokens. (R13 structure.)
// Pos: 3 x float4. Quat: 2 x 256-bit, loads hoisted into the pos load wave.
// Block = 128 threads = 4 rows; grid = BB/4.
// ---------------------------------------------------------------------------
__global__ __launch_bounds__(128) void rot_randomizer_kernel(
    const float* __restrict__ pos,   // [B,T,3]
    const float* __restrict__ quat,  // [B,T,4] xyzw
    float* __restrict__ pos_out,     // [B,T,3]
    float* __restrict__ quat_out,    // [B,T,4] xyzw
    float* __restrict__ R_out,       // [B,3,3]
    uint32_t k0a, uint32_t k0b, uint32_t k1a, uint32_t k1b,
    uint32_t k2a, uint32_t k2b, uint32_t k3a, uint32_t k3b)
{
    const int warp = threadIdx.x >> 5;
    const int lane = threadIdx.x & 31;
    const int b = blockIdx.x * 4 + warp;
    const unsigned FULL = 0xFFFFFFFFu;

    // ------------------ per-row RNG (lanes 0..3) ------------------
    float u = 0.0f;
    if (lane < 4) {
        uint32_t ka = (lane == 0) ? k0a : (lane == 1) ? k1a : (lane == 2) ? k2a : k3a;
        uint32_t kb = (lane == 0) ? k0b : (lane == 1) ? k1b : (lane == 2) ? k2b : k3b;
        u = jax_uniform_at(ka, kb, b);
    }
    const float u0 = __shfl_sync(FULL, u, 0);
    const float u1 = __shfl_sync(FULL, u, 1);
    const float u2 = __shfl_sync(FULL, u, 2);
    const float u3 = __shfl_sync(FULL, u, 3);

    const float PI_F = 3.14159265358979323846f;
    const bool mask = u3 < 0.015625f;  // 1/64
    const float ax = mask ? 0.0f : ((u0 * 2.0f) * PI_F - PI_F);
    const float ay = mask ? 0.0f : ((u1 * 2.0f) * PI_F - PI_F);
    const float az = mask ? 0.0f : ((u2 * 2.0f) * PI_F - PI_F);

    // ---------- 6 accurate sincos evals on lanes 0..5, broadcast ----------
    // (fast __sincosf flips argmax sign decisions -> correctness failure)
    float amine = 0.0f;
    if      (lane == 0) amine = ax;
    else if (lane == 1) amine = ay;
    else if (lane == 2) amine = az;
    else if (lane == 3) amine = 0.5f * ax;
    else if (lane == 4) amine = 0.5f * ay;
    else if (lane == 5) amine = 0.5f * az;
    float s_, c_;
    sincosf(amine, &s_, &c_);
    const float sx  = __shfl_sync(FULL, s_, 0), cx  = __shfl_sync(FULL, c_, 0);
    const float sy  = __shfl_sync(FULL, s_, 1), cy  = __shfl_sync(FULL, c_, 1);
    const float sz  = __shfl_sync(FULL, s_, 2), cz  = __shfl_sync(FULL, c_, 2);
    const float sx2 = __shfl_sync(FULL, s_, 3), cx2 = __shfl_sync(FULL, c_, 3);
    const float sy2 = __shfl_sync(FULL, s_, 4), cy2 = __shfl_sync(FULL, c_, 4);
    const float sz2 = __shfl_sync(FULL, s_, 5), cz2 = __shfl_sync(FULL, c_, 5);

    // --- R = (Rz @ Ry) @ Rx ---
    const float r00 = cz * cy;
    const float r01 = (cz * sy) * sx - sz * cx;
    const float r02 = (cz * sy) * cx + sz * sx;
    const float r10 = sz * cy;
    const float r11 = (sz * sy) * sx + cz * cx;
    const float r12 = (sz * sy) * cx - cz * sx;
    const float r20 = -sy;
    const float r21 = cy * sx;
    const float r22 = cy * cx;

    if (lane == 0) {
        float* Ro = R_out + b * 9;
        Ro[0] = r00; Ro[1] = r01; Ro[2] = r02;
        Ro[3] = r10; Ro[4] = r11; Ro[5] = r12;
        Ro[6] = r20; Ro[7] = r21; Ro[8] = r22;
    }

    // --- r_q = quat(Rz) (x) quat(Ry) (x) quat(Rx), wxyz ---
    const float w1  = cy2 * cx2;
    const float x1q = cy2 * sx2;
    const float y1q = cx2 * sy2;
    const float z1q = -sy2 * sx2;
    const float rw = cz2 * w1  - sz2 * z1q;
    const float rx = cz2 * x1q - sz2 * y1q;
    const float ry = cz2 * y1q + sz2 * x1q;
    const float rz = cz2 * z1q + sz2 * w1;

    const int off  = b * (TT * 3) + lane * 12;
    const int qoff = b * (TT * 4) + lane * 16;

    // ---------- combined load wave: 3 x LDG.128 (pos) + 2 x LDG.256 (quat)
    const float4 A  = *reinterpret_cast<const float4*>(pos + off);
    const float4 Bv = *reinterpret_cast<const float4*>(pos + off + 4);
    const float4 C  = *reinterpret_cast<const float4*>(pos + off + 8);
    float qin[16];
    ldg256(quat + qoff,     qin);
    ldg256(quat + qoff + 8, qin + 8);

    // ------------------- positions: rotate + store -------------------
    {
        const float p0x = A.x,  p0y = A.y,  p0z = A.z;
        const float p1x = A.w,  p1y = Bv.x, p1z = Bv.y;
        const float p2x = Bv.z, p2y = Bv.w, p2z = C.x;
        const float p3x = C.y,  p3y = C.z,  p3z = C.w;

        float4 D, E, F;
        D.x = r00 * p0x + r01 * p0y + r02 * p0z;
        D.y = r10 * p0x + r11 * p0y + r12 * p0z;
        D.z = r20 * p0x + r21 * p0y + r22 * p0z;
        D.w = r00 * p1x + r01 * p1y + r02 * p1z;
        E.x = r10 * p1x + r11 * p1y + r12 * p1z;
        E.y = r20 * p1x + r21 * p1y + r22 * p1z;
        E.z = r00 * p2x + r01 * p2y + r02 * p2z;
        E.w = r10 * p2x + r11 * p2y + r12 * p2z;
        F.x = r20 * p2x + r21 * p2y + r22 * p2z;
        F.y = r00 * p3x + r01 * p3y + r02 * p3z;
        F.z = r10 * p3x + r11 * p3y + r12 * p3z;
        F.w = r20 * p3x + r21 * p3y + r22 * p3z;

        *reinterpret_cast<float4*>(pos_out + off)     = D;
        *reinterpret_cast<float4*>(pos_out + off + 4) = E;
        *reinterpret_cast<float4*>(pos_out + off + 8) = F;
    }

    // ------------------- quats: compose + 2 x 256-bit store ---------------
    {
        float qout[16];
#pragma unroll
        for (int j = 0; j < 4; j++) {
            const float qx = qin[j * 4 + 0], qy = qin[j * 4 + 1],
                        qz = qin[j * 4 + 2], qw = qin[j * 4 + 3];  // xyzw

            // p = r_q (x) q   (wxyz)
            const float pw = rw * qw - rx * qx - ry * qy - rz * qz;
            const float px = rw * qx + rx * qw + ry * qz - rz * qy;
            const float py = rw * qy - rx * qz + ry * qw + rz * qx;
            const float pz = rw * qz + rx * qy - ry * qx + rz * qw;

            // first-max argmax over |pw|,|px|,|py|,|pz| -> sign canonicalization
            const float aw = fabsf(pw), axv = fabsf(px),
                        ayv = fabsf(py), azv = fabsf(pz);
            float bv = aw, bs = pw;
            if (axv > bv) { bv = axv; bs = px; }
            if (ayv > bv) { bv = ayv; bs = py; }
            if (azv > bv) { bv = azv; bs = pz; }

            const float n2 = qx * qx + qy * qy + qz * qz + qw * qw;
            float f = rsqrtf(n2);
            f = (bs < 0.0f) ? -f : f;

            qout[j * 4 + 0] = px * f;
            qout[j * 4 + 1] = py * f;
            qout[j * 4 + 2] = pz * f;
            qout[j * 4 + 3] = pw * f;  // xyzw
        }

        stg256(quat_out + qoff,     qout);
        stg256(quat_out + qoff + 8, qout + 8);
    }
}

// ---------------------------------------------------------------------------
// Host: derive the four _build_R keys from seed 42 (partitionable threefry)
// ---------------------------------------------------------------------------
static void host_threefry(uint32_t k0, uint32_t k1, uint32_t x0, uint32_t x1,
                          uint32_t* o0, uint32_t* o1) {
    threefry2x32(k0, k1, x0, x1);
    *o0 = x0; *o1 = x1;
}

extern "C" void kernel_launch(void* const* d_in, const int* in_sizes, int n_in,
                              void* d_out, int out_size) {
    const float* pos  = (const float*)d_in[0];
    const float* quat = (const float*)d_in[1];
    float* out = (float*)d_out;

    // key = jax.random.key(42) -> (0, 42); sub = split(key)[1]
    uint32_t sa, sb;
    host_threefry(0u, 42u, 0u, 1u, &sa, &sb);

    // k = split(sub, 4): k[j] = full output pair of threefry(sub; 0, j)
    uint32_t kj[4][2];
    for (uint32_t j = 0; j < 4; j++) {
        host_threefry(sa, sb, 0u, j, &kj[j][0], &kj[j][1]);
    }

    float* pos_out  = out;
    float* quat_out = out + (size_t)BB * TT * 3;
    float* R_out    = out + (size_t)BB * TT * 7;

    rot_randomizer_kernel<<<BB / 4, 128>>>(
        pos, quat, pos_out, quat_out, R_out,
        kj[0][0], kj[0][1],
        kj[1][0], kj[1][1],
        kj[2][0], kj[2][1],
        kj[3][0], kj[3][1]);
}